// round 1
// baseline (speedup 1.0000x reference)
#include <cuda_runtime.h>
#include <cuda_bf16.h>
#include <math.h>

#define Bsz 8
#define Cch 256
#define Hh 80
#define Ww 80
#define HW 6400
#define EPS 1e-5f

// ---------------- scratch (device globals: no allocations allowed) ----------
__device__ float g_qkv[(size_t)Bsz * 768 * HW];      // [b,768,hw]
__device__ float g_stacked[(size_t)Bsz * HW * 256];  // [b,hw,s(4),c(64)]
__device__ float g_y2[(size_t)Bsz * HW * 256];       // [b,hw,256]
__device__ float g_x1[(size_t)Bsz * 256 * HW];       // [b,256,hw]
__device__ float g_h[(size_t)Bsz * 512 * HW];        // [b,512,hw]

// ---------------- GEMM: C[b,o,n] = sum_k A[o,k]*B[b,k,n] (+epilogue) --------
// TRANSB: B stored [b,n,k] row-major (k contiguous) instead of [b,k,n].
enum { EPI_BIAS = 0, EPI_BIAS_ADD = 1, EPI_BN_SILU = 2, EPI_BN_ADD = 3 };

template <int EPI, bool TRANSB>
__global__ __launch_bounds__(256) void gemm_k(
    const float* __restrict__ A, const float* __restrict__ B,
    float* __restrict__ C, int M, int N, int K,
    const float* __restrict__ p0, const float* __restrict__ p1,
    const float* __restrict__ p2, const float* __restrict__ p3,
    const float* __restrict__ add)
{
    __shared__ float sA[16][64];
    __shared__ float sB[16][68];

    const int bz = blockIdx.z;
    const float* Bb = B + (size_t)bz * K * N;
    float* Cb = C + (size_t)bz * M * N;
    const float* addb = (EPI == EPI_BIAS_ADD || EPI == EPI_BN_ADD)
                            ? add + (size_t)bz * M * N : nullptr;

    const int m0 = blockIdx.y * 64;
    const int n0 = blockIdx.x * 64;
    const int tid = threadIdx.x;
    const int ty = tid >> 4, tx = tid & 15;

    const int aRow = tid >> 2, aK4 = (tid & 3) << 2;   // A tile loader
    const int bK = tid >> 4, bN4 = (tid & 15) << 2;    // B (k,n) loader
    const int bRowT = tid >> 2, bK4 = (tid & 3) << 2;  // B (n,k) loader

    float acc[4][4];
#pragma unroll
    for (int i = 0; i < 4; i++)
#pragma unroll
        for (int j = 0; j < 4; j++) acc[i][j] = 0.f;

    for (int k0 = 0; k0 < K; k0 += 16) {
        float4 av = *(const float4*)(A + (size_t)(m0 + aRow) * K + k0 + aK4);
        sA[aK4 + 0][aRow] = av.x;
        sA[aK4 + 1][aRow] = av.y;
        sA[aK4 + 2][aRow] = av.z;
        sA[aK4 + 3][aRow] = av.w;
        if (TRANSB) {
            float4 bv = *(const float4*)(Bb + (size_t)(n0 + bRowT) * K + k0 + bK4);
            sB[bK4 + 0][bRowT] = bv.x;
            sB[bK4 + 1][bRowT] = bv.y;
            sB[bK4 + 2][bRowT] = bv.z;
            sB[bK4 + 3][bRowT] = bv.w;
        } else {
            float4 bv = *(const float4*)(Bb + (size_t)(k0 + bK) * N + n0 + bN4);
            *(float4*)&sB[bK][bN4] = bv;
        }
        __syncthreads();
#pragma unroll
        for (int k = 0; k < 16; k++) {
            float4 a = *(const float4*)&sA[k][ty << 2];
            float4 b = *(const float4*)&sB[k][tx << 2];
            acc[0][0] += a.x * b.x; acc[0][1] += a.x * b.y; acc[0][2] += a.x * b.z; acc[0][3] += a.x * b.w;
            acc[1][0] += a.y * b.x; acc[1][1] += a.y * b.y; acc[1][2] += a.y * b.z; acc[1][3] += a.y * b.w;
            acc[2][0] += a.z * b.x; acc[2][1] += a.z * b.y; acc[2][2] += a.z * b.z; acc[2][3] += a.z * b.w;
            acc[3][0] += a.w * b.x; acc[3][1] += a.w * b.y; acc[3][2] += a.w * b.z; acc[3][3] += a.w * b.w;
        }
        __syncthreads();
    }

#pragma unroll
    for (int i = 0; i < 4; i++) {
        const int o = m0 + (ty << 2) + i;
        float e_scale = 1.f, e_shift = 0.f;
        if (EPI == EPI_BIAS || EPI == EPI_BIAS_ADD) {
            e_shift = p0[o];
        } else {
            float inv = p0[o] * rsqrtf(p3[o] + EPS);
            e_scale = inv;
            e_shift = p1[o] - p2[o] * inv;
        }
#pragma unroll
        for (int j = 0; j < 4; j++) {
            const int n = n0 + (tx << 2) + j;
            float z = acc[i][j] * e_scale + e_shift;
            if (EPI == EPI_BN_SILU) z = z / (1.f + __expf(-z));
            if (EPI == EPI_BIAS_ADD || EPI == EPI_BN_ADD)
                z += addb[(size_t)o * N + n];
            Cb[(size_t)o * N + n] = z;
        }
    }
}

// ---------------- dilated 3x3 local attention (one thread per pixel) --------
__global__ __launch_bounds__(256) void attn_k(const float* __restrict__ qkv,
                                              float* __restrict__ stacked)
{
    const int i = blockIdx.y;           // dilation index 0..3
    const int b = blockIdx.z;
    const int n = blockIdx.x * 256 + threadIdx.x;
    const int h = n / Ww, w = n % Ww;
    const int r = 1 << i;               // DIL = 1,2,4,8

    const float* qb = qkv + ((size_t)b * 768 + i * 64) * HW;
    const float* kb = qb + (size_t)256 * HW;
    const float* vb = qb + (size_t)512 * HW;

    int noff[9];
#pragma unroll
    for (int dy = 0; dy < 3; dy++)
#pragma unroll
        for (int dx = 0; dx < 3; dx++) {
            int hh = h + (dy - 1) * r, ww = w + (dx - 1) * r;
            noff[dy * 3 + dx] =
                (hh >= 0 && hh < Hh && ww >= 0 && ww < Ww) ? hh * Ww + ww : -1;
        }

    float logit[9];
#pragma unroll
    for (int j = 0; j < 9; j++) logit[j] = 0.f;

    for (int c = 0; c < 64; c++) {
        const float q = qb[(size_t)c * HW + n];
#pragma unroll
        for (int j = 0; j < 9; j++) {
            float kv = (noff[j] >= 0) ? kb[(size_t)c * HW + noff[j]] : 0.f;
            logit[j] += q * kv;
        }
    }

    const float scale = 0.125f;  // hd=64 -> 64^-0.5
    float mx = -1e30f;
#pragma unroll
    for (int j = 0; j < 9; j++) {
        logit[j] *= scale;
        mx = fmaxf(mx, logit[j]);
    }
    float p[9], sum = 0.f;
#pragma unroll
    for (int j = 0; j < 9; j++) { p[j] = __expf(logit[j] - mx); sum += p[j]; }
    const float inv = 1.f / sum;
#pragma unroll
    for (int j = 0; j < 9; j++) p[j] *= inv;

    float* ob = stacked + (((size_t)b * HW + n) * 4 + i) * 64;
    for (int c = 0; c < 64; c++) {
        float o = 0.f;
#pragma unroll
        for (int j = 0; j < 9; j++) {
            float vv = (noff[j] >= 0) ? vb[(size_t)c * HW + noff[j]] : 0.f;
            o += p[j] * vv;
        }
        ob[c] = o;
    }
}

// ---------------- fc scale-fuse + residual + LayerNorm(64) ------------------
// one block per pixel; warp t handles scale-group t; lane covers c, c+32
__global__ __launch_bounds__(128) void fuse_ln_k(
    const float* __restrict__ stacked, float* __restrict__ y2,
    const float* __restrict__ fc_w, const float* __restrict__ fc_b,
    const float* __restrict__ ln_g, const float* __restrict__ ln_b)
{
    const int p = blockIdx.x;
    const float* sp = stacked + (size_t)p * 256;
    const int t = threadIdx.x >> 5, lane = threadIdx.x & 31;

    float f0 = fc_b[t], f1 = f0;
    float r0 = 0.f, r1 = 0.f;
#pragma unroll
    for (int s = 0; s < 4; s++) {
        float w = fc_w[t * 4 + s];
        float x0 = sp[s * 64 + lane];
        float x1 = sp[s * 64 + lane + 32];
        f0 += w * x0;
        f1 += w * x1;
        if (s == t) { r0 = x0; r1 = x1; }
    }
    f0 += r0;
    f1 += r1;

    float sum = f0 + f1, sq = f0 * f0 + f1 * f1;
#pragma unroll
    for (int o = 16; o; o >>= 1) {
        sum += __shfl_xor_sync(0xffffffffu, sum, o);
        sq  += __shfl_xor_sync(0xffffffffu, sq, o);
    }
    const float mu = sum * (1.f / 64.f);
    const float var = sq * (1.f / 64.f) - mu * mu;
    const float rinv = rsqrtf(var + EPS);

    y2[(size_t)p * 256 + t * 64 + lane] =
        (f0 - mu) * rinv * ln_g[lane] + ln_b[lane];
    y2[(size_t)p * 256 + t * 64 + lane + 32] =
        (f1 - mu) * rinv * ln_g[lane + 32] + ln_b[lane + 32];
}

// ---------------- launch ----------------------------------------------------
extern "C" void kernel_launch(void* const* d_in, const int* in_sizes, int n_in,
                              void* d_out, int out_size)
{
    const float* x      = (const float*)d_in[0];
    const float* qkv_w  = (const float*)d_in[1];
    const float* qkv_b  = (const float*)d_in[2];
    const float* fc_w   = (const float*)d_in[3];
    const float* fc_b   = (const float*)d_in[4];
    const float* ln_g   = (const float*)d_in[5];
    const float* ln_b   = (const float*)d_in[6];
    const float* proj_w = (const float*)d_in[7];
    const float* proj_b = (const float*)d_in[8];
    const float* w1     = (const float*)d_in[9];
    const float* bn1_g  = (const float*)d_in[10];
    const float* bn1_b  = (const float*)d_in[11];
    const float* bn1_m  = (const float*)d_in[12];
    const float* bn1_v  = (const float*)d_in[13];
    const float* w2     = (const float*)d_in[14];
    const float* bn2_g  = (const float*)d_in[15];
    const float* bn2_b  = (const float*)d_in[16];
    const float* bn2_m  = (const float*)d_in[17];
    const float* bn2_v  = (const float*)d_in[18];
    float* out = (float*)d_out;

    void *p_qkv, *p_st, *p_y2, *p_x1, *p_h;
    cudaGetSymbolAddress(&p_qkv, g_qkv);
    cudaGetSymbolAddress(&p_st, g_stacked);
    cudaGetSymbolAddress(&p_y2, g_y2);
    cudaGetSymbolAddress(&p_x1, g_x1);
    cudaGetSymbolAddress(&p_h, g_h);
    float* qkv = (float*)p_qkv;
    float* stk = (float*)p_st;
    float* y2  = (float*)p_y2;
    float* x1  = (float*)p_x1;
    float* hb  = (float*)p_h;

    // 1) qkv = qkv_w @ x + qkv_b           (M=768, N=6400, K=256, per batch)
    gemm_k<EPI_BIAS, false><<<dim3(100, 12, Bsz), 256>>>(
        qkv_w, x, qkv, 768, HW, 256, qkv_b, nullptr, nullptr, nullptr, nullptr);

    // 2) dilated local attention -> stacked [b,hw,s,c]
    attn_k<<<dim3(25, 4, Bsz), 256>>>(qkv, stk);

    // 3) fc fuse + residual + LN -> y2 [b,hw,256]
    fuse_ln_k<<<Bsz * HW, 128>>>(stk, y2, fc_w, fc_b, ln_g, ln_b);

    // 4) x1 = x + proj_w @ y2^T + proj_b   (B transposed: y2 is [n,k])
    gemm_k<EPI_BIAS_ADD, true><<<dim3(100, 4, Bsz), 256>>>(
        proj_w, y2, x1, 256, HW, 256, proj_b, nullptr, nullptr, nullptr, x);

    // 5) h = silu(bn1(w1 @ x1))            (M=512, K=256)
    gemm_k<EPI_BN_SILU, false><<<dim3(100, 8, Bsz), 256>>>(
        w1, x1, hb, 512, HW, 256, bn1_g, bn1_b, bn1_m, bn1_v, nullptr);

    // 6) out = x1 + bn2(w2 @ h)            (M=256, K=512)
    gemm_k<EPI_BN_ADD, false><<<dim3(100, 4, Bsz), 256>>>(
        w2, hb, out, 256, HW, 512, bn2_g, bn2_b, bn2_m, bn2_v, x1);
}

// round 2
// speedup vs baseline: 1.3184x; 1.3184x over previous
#include <cuda_runtime.h>
#include <cuda_bf16.h>
#include <math.h>

#define Bsz 8
#define Cch 256
#define Hh 80
#define Ww 80
#define HW 6400
#define EPS 1e-5f

// ---------------- scratch (device globals: no allocations allowed) ----------
__device__ float g_qkv[(size_t)Bsz * 768 * HW];      // [b,768,hw]
__device__ float g_stacked[(size_t)Bsz * HW * 256];  // [b,hw,s(4),c(64)]
__device__ float g_y2[(size_t)Bsz * HW * 256];       // [b,hw,256]
__device__ float g_y2t[(size_t)Bsz * 256 * HW];      // [b,256,hw]
__device__ float g_x1[(size_t)Bsz * 256 * HW];       // [b,256,hw]
__device__ float g_h[(size_t)Bsz * 512 * HW];        // [b,512,hw]
// transposed weights: qkvT[256,768] projT[256,256] w1T[256,512] w2T[512,256]
__device__ float g_wt[256 * 768 + 256 * 256 + 256 * 512 + 512 * 256];

// ---------------- helpers ----------------------------------------------------
__device__ __forceinline__ unsigned s2u(const void* p) {
    return (unsigned)__cvta_generic_to_shared(p);
}
__device__ __forceinline__ void cpa16(unsigned s, const float* g) {
    asm volatile("cp.async.cg.shared.global [%0], [%1], 16;\n" ::"r"(s), "l"(g));
}
#define CP_COMMIT asm volatile("cp.async.commit_group;\n" ::)
#define CP_WAIT1 asm volatile("cp.async.wait_group 1;\n" ::)
#define CP_WAIT0 asm volatile("cp.async.wait_group 0;\n" ::)

#define FFMA2(d, a, b) \
    asm("fma.rn.f32x2 %0, %1, %2, %0;" : "+l"(d) : "l"(a), "l"(b))
#define DUP2(d, f) \
    asm("mov.b64 %0, {%1, %1};" : "=l"(d) : "r"(__float_as_uint(f)))

// ---------------- generic transpose: src[R,C] -> dst[C,R], batched ----------
__global__ void transpose_k(const float* __restrict__ src,
                            float* __restrict__ dst, int R, int C)
{
    __shared__ float t[32][33];
    const size_t bo = (size_t)blockIdx.z * R * C;
    const int c0 = blockIdx.x * 32, r0 = blockIdx.y * 32;
#pragma unroll
    for (int i = threadIdx.y; i < 32; i += 8)
        t[i][threadIdx.x] = src[bo + (size_t)(r0 + i) * C + c0 + threadIdx.x];
    __syncthreads();
#pragma unroll
    for (int i = threadIdx.y; i < 32; i += 8)
        dst[bo + (size_t)(c0 + i) * R + r0 + threadIdx.x] = t[threadIdx.x][i];
}

// ---------------- GEMM: C[b,m,n] = sum_k At[k,m]*B[b,k,n] (+epilogue) -------
enum { EPI_BIAS = 0, EPI_BIAS_ADD = 1, EPI_BN_SILU = 2, EPI_BN_ADD = 3 };

template <int EPI>
__global__ __launch_bounds__(256) void gemm_k(
    const float* __restrict__ At, const float* __restrict__ B,
    float* __restrict__ C, int M, int N, int K,
    const float* __restrict__ p0, const float* __restrict__ p1,
    const float* __restrict__ p2, const float* __restrict__ p3,
    const float* __restrict__ add)
{
    __shared__ float sA[2][16][128];
    __shared__ float sB[2][16][128];

    const int bz = blockIdx.z;
    const float* Bb = B + (size_t)bz * K * N;
    float* Cb = C + (size_t)bz * M * N;
    const float* addb = (EPI == EPI_BIAS_ADD || EPI == EPI_BN_ADD)
                            ? add + (size_t)bz * M * N : nullptr;

    const int m0 = blockIdx.y * 128;
    const int n0 = blockIdx.x * 128;
    const int tid = threadIdx.x;
    const int ty = tid >> 4, tx = tid & 15;

    // loader mapping: row lk (0..15) within k-tile, 8 floats at col lc
    const int lk = tid >> 4;
    const int lc = (tid & 15) * 8;
    const float* gA = At + (size_t)lk * M + m0 + lc;
    const float* gB = Bb + (size_t)lk * N + n0 + lc;
    const unsigned saw = s2u(&sA[0][lk][lc]);
    const unsigned sbw = s2u(&sB[0][lk][lc]);

    unsigned long long acc[8][4];
#pragma unroll
    for (int i = 0; i < 8; i++)
#pragma unroll
        for (int j = 0; j < 4; j++) acc[i][j] = 0ULL;

    const int T = K >> 4;

    // prologue: tile 0 -> buf 0
    cpa16(saw, gA);
    cpa16(saw + 16, gA + 4);
    cpa16(sbw, gB);
    cpa16(sbw + 16, gB + 4);
    CP_COMMIT;

    for (int t = 0; t < T; t++) {
        if (t + 1 < T) {
            const int nb = (t + 1) & 1;
            const size_t ko = (size_t)(t + 1) * 16;
            cpa16(saw + nb * 8192, gA + ko * M);
            cpa16(saw + nb * 8192 + 16, gA + ko * M + 4);
            cpa16(sbw + nb * 8192, gB + ko * N);
            cpa16(sbw + nb * 8192 + 16, gB + ko * N + 4);
            CP_COMMIT;
            CP_WAIT1;
        } else {
            CP_WAIT0;
        }
        __syncthreads();

        const float(*cA)[128] = sA[t & 1];
        const float(*cB)[128] = sB[t & 1];
#pragma unroll
        for (int k = 0; k < 16; k++) {
            float4 af0 = *(const float4*)&cA[k][ty * 8];
            float4 af1 = *(const float4*)&cA[k][ty * 8 + 4];
            ulonglong2 bq0 = *(const ulonglong2*)&cB[k][tx * 8];
            ulonglong2 bq1 = *(const ulonglong2*)&cB[k][tx * 8 + 4];
            unsigned long long a2;
#define ROWF(i, av)                      \
    DUP2(a2, av);                        \
    FFMA2(acc[i][0], a2, bq0.x);         \
    FFMA2(acc[i][1], a2, bq0.y);         \
    FFMA2(acc[i][2], a2, bq1.x);         \
    FFMA2(acc[i][3], a2, bq1.y);
            ROWF(0, af0.x) ROWF(1, af0.y) ROWF(2, af0.z) ROWF(3, af0.w)
            ROWF(4, af1.x) ROWF(5, af1.y) ROWF(6, af1.z) ROWF(7, af1.w)
#undef ROWF
        }
        __syncthreads();
    }

    // epilogue
    const int nb = n0 + tx * 8;
#pragma unroll
    for (int i = 0; i < 8; i++) {
        const int o = m0 + ty * 8 + i;
        float e_scale = 1.f, e_shift = 0.f;
        if (EPI == EPI_BIAS || EPI == EPI_BIAS_ADD) {
            e_shift = p0[o];
        } else {
            float inv = p0[o] * rsqrtf(p3[o] + EPS);
            e_scale = inv;
            e_shift = p1[o] - p2[o] * inv;
        }
        float2 v[4];
#pragma unroll
        for (int j = 0; j < 4; j++) {
            float2 f = *(float2*)&acc[i][j];
            f.x = f.x * e_scale + e_shift;
            f.y = f.y * e_scale + e_shift;
            if (EPI == EPI_BN_SILU) {
                f.x = f.x / (1.f + __expf(-f.x));
                f.y = f.y / (1.f + __expf(-f.y));
            }
            v[j] = f;
        }
        float4 r0 = make_float4(v[0].x, v[0].y, v[1].x, v[1].y);
        float4 r1 = make_float4(v[2].x, v[2].y, v[3].x, v[3].y);
        if (EPI == EPI_BIAS_ADD || EPI == EPI_BN_ADD) {
            float4 a0 = *(const float4*)&addb[(size_t)o * N + nb];
            float4 a1 = *(const float4*)&addb[(size_t)o * N + nb + 4];
            r0.x += a0.x; r0.y += a0.y; r0.z += a0.z; r0.w += a0.w;
            r1.x += a1.x; r1.y += a1.y; r1.z += a1.z; r1.w += a1.w;
        }
        *(float4*)&Cb[(size_t)o * N + nb] = r0;
        *(float4*)&Cb[(size_t)o * N + nb + 4] = r1;
    }
}

// ---------------- dilated 3x3 local attention (one thread per pixel) --------
__global__ __launch_bounds__(256) void attn_k(const float* __restrict__ qkv,
                                              float* __restrict__ stacked)
{
    const int i = blockIdx.y;           // dilation index 0..3
    const int b = blockIdx.z;
    const int n = blockIdx.x * 256 + threadIdx.x;
    const int h = n / Ww, w = n % Ww;
    const int r = 1 << i;               // DIL = 1,2,4,8

    const float* qb = qkv + ((size_t)b * 768 + i * 64) * HW;
    const float* kb = qb + (size_t)256 * HW;
    const float* vb = qb + (size_t)512 * HW;

    int noff[9];
#pragma unroll
    for (int dy = 0; dy < 3; dy++)
#pragma unroll
        for (int dx = 0; dx < 3; dx++) {
            int hh = h + (dy - 1) * r, ww = w + (dx - 1) * r;
            noff[dy * 3 + dx] =
                (hh >= 0 && hh < Hh && ww >= 0 && ww < Ww) ? hh * Ww + ww : -1;
        }

    float logit[9];
#pragma unroll
    for (int j = 0; j < 9; j++) logit[j] = 0.f;

    for (int c = 0; c < 64; c++) {
        const float q = qb[(size_t)c * HW + n];
#pragma unroll
        for (int j = 0; j < 9; j++) {
            float kv = (noff[j] >= 0) ? kb[(size_t)c * HW + noff[j]] : 0.f;
            logit[j] += q * kv;
        }
    }

    const float scale = 0.125f;  // hd=64 -> 64^-0.5
    float mx = -1e30f;
#pragma unroll
    for (int j = 0; j < 9; j++) {
        logit[j] *= scale;
        mx = fmaxf(mx, logit[j]);
    }
    float p[9], sum = 0.f;
#pragma unroll
    for (int j = 0; j < 9; j++) { p[j] = __expf(logit[j] - mx); sum += p[j]; }
    const float inv = 1.f / sum;
#pragma unroll
    for (int j = 0; j < 9; j++) p[j] *= inv;

    float* ob = stacked + (((size_t)b * HW + n) * 4 + i) * 64;
    for (int c = 0; c < 64; c++) {
        float o = 0.f;
#pragma unroll
        for (int j = 0; j < 9; j++) {
            float vv = (noff[j] >= 0) ? vb[(size_t)c * HW + noff[j]] : 0.f;
            o += p[j] * vv;
        }
        ob[c] = o;
    }
}

// ---------------- fc scale-fuse + residual + LayerNorm(64) ------------------
__global__ __launch_bounds__(128) void fuse_ln_k(
    const float* __restrict__ stacked, float* __restrict__ y2,
    const float* __restrict__ fc_w, const float* __restrict__ fc_b,
    const float* __restrict__ ln_g, const float* __restrict__ ln_b)
{
    const int p = blockIdx.x;
    const float* sp = stacked + (size_t)p * 256;
    const int t = threadIdx.x >> 5, lane = threadIdx.x & 31;

    float f0 = fc_b[t], f1 = f0;
    float r0 = 0.f, r1 = 0.f;
#pragma unroll
    for (int s = 0; s < 4; s++) {
        float w = fc_w[t * 4 + s];
        float x0 = sp[s * 64 + lane];
        float x1 = sp[s * 64 + lane + 32];
        f0 += w * x0;
        f1 += w * x1;
        if (s == t) { r0 = x0; r1 = x1; }
    }
    f0 += r0;
    f1 += r1;

    float sum = f0 + f1, sq = f0 * f0 + f1 * f1;
#pragma unroll
    for (int o = 16; o; o >>= 1) {
        sum += __shfl_xor_sync(0xffffffffu, sum, o);
        sq  += __shfl_xor_sync(0xffffffffu, sq, o);
    }
    const float mu = sum * (1.f / 64.f);
    const float var = sq * (1.f / 64.f) - mu * mu;
    const float rinv = rsqrtf(var + EPS);

    y2[(size_t)p * 256 + t * 64 + lane] =
        (f0 - mu) * rinv * ln_g[lane] + ln_b[lane];
    y2[(size_t)p * 256 + t * 64 + lane + 32] =
        (f1 - mu) * rinv * ln_g[lane + 32] + ln_b[lane + 32];
}

// ---------------- launch ----------------------------------------------------
extern "C" void kernel_launch(void* const* d_in, const int* in_sizes, int n_in,
                              void* d_out, int out_size)
{
    const float* x      = (const float*)d_in[0];
    const float* qkv_w  = (const float*)d_in[1];
    const float* qkv_b  = (const float*)d_in[2];
    const float* fc_w   = (const float*)d_in[3];
    const float* fc_b   = (const float*)d_in[4];
    const float* ln_g   = (const float*)d_in[5];
    const float* ln_b   = (const float*)d_in[6];
    const float* proj_w = (const float*)d_in[7];
    const float* proj_b = (const float*)d_in[8];
    const float* w1     = (const float*)d_in[9];
    const float* bn1_g  = (const float*)d_in[10];
    const float* bn1_b  = (const float*)d_in[11];
    const float* bn1_m  = (const float*)d_in[12];
    const float* bn1_v  = (const float*)d_in[13];
    const float* w2     = (const float*)d_in[14];
    const float* bn2_g  = (const float*)d_in[15];
    const float* bn2_b  = (const float*)d_in[16];
    const float* bn2_m  = (const float*)d_in[17];
    const float* bn2_v  = (const float*)d_in[18];
    float* out = (float*)d_out;

    void *p_qkv, *p_st, *p_y2, *p_y2t, *p_x1, *p_h, *p_wt;
    cudaGetSymbolAddress(&p_qkv, g_qkv);
    cudaGetSymbolAddress(&p_st, g_stacked);
    cudaGetSymbolAddress(&p_y2, g_y2);
    cudaGetSymbolAddress(&p_y2t, g_y2t);
    cudaGetSymbolAddress(&p_x1, g_x1);
    cudaGetSymbolAddress(&p_h, g_h);
    cudaGetSymbolAddress(&p_wt, g_wt);
    float* qkv = (float*)p_qkv;
    float* stk = (float*)p_st;
    float* y2  = (float*)p_y2;
    float* y2t = (float*)p_y2t;
    float* x1  = (float*)p_x1;
    float* hb  = (float*)p_h;
    float* qkvT = (float*)p_wt;
    float* projT = qkvT + 256 * 768;
    float* w1T   = projT + 256 * 256;
    float* w2T   = w1T + 256 * 512;

    dim3 tb(32, 8);
    // 0) transpose weights: W[M,K] -> Wt[K,M]
    transpose_k<<<dim3(256 / 32, 768 / 32, 1), tb>>>(qkv_w, qkvT, 768, 256);
    transpose_k<<<dim3(256 / 32, 256 / 32, 1), tb>>>(proj_w, projT, 256, 256);
    transpose_k<<<dim3(256 / 32, 512 / 32, 1), tb>>>(w1, w1T, 512, 256);
    transpose_k<<<dim3(512 / 32, 256 / 32, 1), tb>>>(w2, w2T, 256, 512);

    // 1) qkv = qkv_w @ x + qkv_b           (M=768, N=6400, K=256)
    gemm_k<EPI_BIAS><<<dim3(50, 6, Bsz), 256>>>(
        qkvT, x, qkv, 768, HW, 256, qkv_b, nullptr, nullptr, nullptr, nullptr);

    // 2) dilated local attention -> stacked [b,hw,s,c]
    attn_k<<<dim3(25, 4, Bsz), 256>>>(qkv, stk);

    // 3) fc fuse + residual + LN -> y2 [b,hw,256]
    fuse_ln_k<<<Bsz * HW, 128>>>(stk, y2, fc_w, fc_b, ln_g, ln_b);

    // 3b) transpose y2 -> y2t [b,256,hw]
    transpose_k<<<dim3(256 / 32, HW / 32, Bsz), tb>>>(y2, y2t, HW, 256);

    // 4) x1 = x + proj_w @ y2t + proj_b    (M=256, N=6400, K=256)
    gemm_k<EPI_BIAS_ADD><<<dim3(50, 2, Bsz), 256>>>(
        projT, y2t, x1, 256, HW, 256, proj_b, nullptr, nullptr, nullptr, x);

    // 5) h = silu(bn1(w1 @ x1))            (M=512, K=256)
    gemm_k<EPI_BN_SILU><<<dim3(50, 4, Bsz), 256>>>(
        w1T, x1, hb, 512, HW, 256, bn1_g, bn1_b, bn1_m, bn1_v, nullptr);

    // 6) out = x1 + bn2(w2 @ h)            (M=256, K=512)
    gemm_k<EPI_BN_ADD><<<dim3(50, 2, Bsz), 256>>>(
        w2T, hb, out, 256, HW, 512, bn2_g, bn2_b, bn2_m, bn2_v, x1);
}

// round 3
// speedup vs baseline: 1.3198x; 1.0010x over previous
#include <cuda_runtime.h>
#include <cuda_bf16.h>
#include <math.h>

#define Bsz 8
#define Cch 256
#define Hh 80
#define Ww 80
#define HW 6400
#define EPS 1e-5f

// ---------------- scratch (device globals: no allocations allowed) ----------
__device__ float g_qkv[(size_t)Bsz * 768 * HW];      // [b,768,hw]
__device__ float g_stacked[(size_t)Bsz * HW * 256];  // [b,hw,s(4),c(64)]
__device__ float g_y2[(size_t)Bsz * HW * 256];       // [b,hw,256]
__device__ float g_y2t[(size_t)Bsz * 256 * HW];      // [b,256,hw]
__device__ float g_x1[(size_t)Bsz * 256 * HW];       // [b,256,hw]
__device__ float g_h[(size_t)Bsz * 512 * HW];        // [b,512,hw]
// transposed weights: qkvT[256,768] projT[256,256] w1T[256,512] w2T[512,256]
__device__ float g_wt[256 * 768 + 256 * 256 + 256 * 512 + 512 * 256];

// ---------------- helpers ----------------------------------------------------
__device__ __forceinline__ unsigned s2u(const void* p) {
    return (unsigned)__cvta_generic_to_shared(p);
}
__device__ __forceinline__ void cpa16(unsigned s, const float* g) {
    asm volatile("cp.async.cg.shared.global [%0], [%1], 16;\n" ::"r"(s), "l"(g));
}
#define CP_COMMIT asm volatile("cp.async.commit_group;\n" ::)
#define CP_WAIT1 asm volatile("cp.async.wait_group 1;\n" ::)
#define CP_WAIT0 asm volatile("cp.async.wait_group 0;\n" ::)

#define FFMA2(d, a, b) \
    asm("fma.rn.f32x2 %0, %1, %2, %0;" : "+l"(d) : "l"(a), "l"(b))
#define DUP2(d, f) \
    asm("mov.b64 %0, {%1, %1};" : "=l"(d) : "r"(__float_as_uint(f)))

// ---------------- generic transpose: src[R,C] -> dst[C,R], batched ----------
__global__ void transpose_k(const float* __restrict__ src,
                            float* __restrict__ dst, int R, int C)
{
    __shared__ float t[32][33];
    const size_t bo = (size_t)blockIdx.z * R * C;
    const int c0 = blockIdx.x * 32, r0 = blockIdx.y * 32;
#pragma unroll
    for (int i = threadIdx.y; i < 32; i += 8)
        t[i][threadIdx.x] = src[bo + (size_t)(r0 + i) * C + c0 + threadIdx.x];
    __syncthreads();
#pragma unroll
    for (int i = threadIdx.y; i < 32; i += 8)
        dst[bo + (size_t)(c0 + i) * R + r0 + threadIdx.x] = t[threadIdx.x][i];
}

// ---------------- GEMM: C[b,m,n] = sum_k At[k,m]*B[b,k,n] (+epilogue) -------
enum { EPI_BIAS = 0, EPI_BIAS_ADD = 1, EPI_BN_SILU = 2, EPI_BN_ADD = 3 };

template <int EPI>
__global__ __launch_bounds__(256) void gemm_k(
    const float* __restrict__ At, const float* __restrict__ B,
    float* __restrict__ C, int M, int N, int K,
    const float* __restrict__ p0, const float* __restrict__ p1,
    const float* __restrict__ p2, const float* __restrict__ p3,
    const float* __restrict__ add)
{
    __shared__ float sA[2][16][128];
    __shared__ float sB[2][16][128];

    const int bz = blockIdx.z;
    const float* Bb = B + (size_t)bz * K * N;
    float* Cb = C + (size_t)bz * M * N;
    const float* addb = (EPI == EPI_BIAS_ADD || EPI == EPI_BN_ADD)
                            ? add + (size_t)bz * M * N : nullptr;

    const int m0 = blockIdx.y * 128;
    const int n0 = blockIdx.x * 128;
    const int tid = threadIdx.x;
    const int ty = tid >> 4, tx = tid & 15;

    // loader mapping: row lk (0..15) within k-tile, 8 floats at col lc
    const int lk = tid >> 4;
    const int lc = (tid & 15) * 8;
    const float* gA = At + (size_t)lk * M + m0 + lc;
    const float* gB = Bb + (size_t)lk * N + n0 + lc;
    const unsigned saw = s2u(&sA[0][lk][lc]);
    const unsigned sbw = s2u(&sB[0][lk][lc]);

    unsigned long long acc[8][4];
#pragma unroll
    for (int i = 0; i < 8; i++)
#pragma unroll
        for (int j = 0; j < 4; j++) acc[i][j] = 0ULL;

    const int T = K >> 4;

    // prologue: tile 0 -> buf 0
    cpa16(saw, gA);
    cpa16(saw + 16, gA + 4);
    cpa16(sbw, gB);
    cpa16(sbw + 16, gB + 4);
    CP_COMMIT;

    for (int t = 0; t < T; t++) {
        if (t + 1 < T) {
            const int nb = (t + 1) & 1;
            const size_t ko = (size_t)(t + 1) * 16;
            cpa16(saw + nb * 8192, gA + ko * M);
            cpa16(saw + nb * 8192 + 16, gA + ko * M + 4);
            cpa16(sbw + nb * 8192, gB + ko * N);
            cpa16(sbw + nb * 8192 + 16, gB + ko * N + 4);
            CP_COMMIT;
            CP_WAIT1;
        } else {
            CP_WAIT0;
        }
        __syncthreads();

        const float(*cA)[128] = sA[t & 1];
        const float(*cB)[128] = sB[t & 1];
#pragma unroll
        for (int k = 0; k < 16; k++) {
            float4 af0 = *(const float4*)&cA[k][ty * 8];
            float4 af1 = *(const float4*)&cA[k][ty * 8 + 4];
            ulonglong2 bq0 = *(const ulonglong2*)&cB[k][tx * 8];
            ulonglong2 bq1 = *(const ulonglong2*)&cB[k][tx * 8 + 4];
            unsigned long long a2;
#define ROWF(i, av)                      \
    DUP2(a2, av);                        \
    FFMA2(acc[i][0], a2, bq0.x);         \
    FFMA2(acc[i][1], a2, bq0.y);         \
    FFMA2(acc[i][2], a2, bq1.x);         \
    FFMA2(acc[i][3], a2, bq1.y);
            ROWF(0, af0.x) ROWF(1, af0.y) ROWF(2, af0.z) ROWF(3, af0.w)
            ROWF(4, af1.x) ROWF(5, af1.y) ROWF(6, af1.z) ROWF(7, af1.w)
#undef ROWF
        }
        __syncthreads();
    }

    // epilogue
    const int nb = n0 + tx * 8;
#pragma unroll
    for (int i = 0; i < 8; i++) {
        const int o = m0 + ty * 8 + i;
        float e_scale = 1.f, e_shift = 0.f;
        if (EPI == EPI_BIAS || EPI == EPI_BIAS_ADD) {
            e_shift = p0[o];
        } else {
            float inv = p0[o] * rsqrtf(p3[o] + EPS);
            e_scale = inv;
            e_shift = p1[o] - p2[o] * inv;
        }
        float2 v[4];
#pragma unroll
        for (int j = 0; j < 4; j++) {
            float2 f = *(float2*)&acc[i][j];
            f.x = f.x * e_scale + e_shift;
            f.y = f.y * e_scale + e_shift;
            if (EPI == EPI_BN_SILU) {
                f.x = f.x / (1.f + __expf(-f.x));
                f.y = f.y / (1.f + __expf(-f.y));
            }
            v[j] = f;
        }
        float4 r0 = make_float4(v[0].x, v[0].y, v[1].x, v[1].y);
        float4 r1 = make_float4(v[2].x, v[2].y, v[3].x, v[3].y);
        if (EPI == EPI_BIAS_ADD || EPI == EPI_BN_ADD) {
            float4 a0 = *(const float4*)&addb[(size_t)o * N + nb];
            float4 a1 = *(const float4*)&addb[(size_t)o * N + nb + 4];
            r0.x += a0.x; r0.y += a0.y; r0.z += a0.z; r0.w += a0.w;
            r1.x += a1.x; r1.y += a1.y; r1.z += a1.z; r1.w += a1.w;
        }
        *(float4*)&Cb[(size_t)o * N + nb] = r0;
        *(float4*)&Cb[(size_t)o * N + nb + 4] = r1;
    }
}

// ---------------- dilated 3x3 local attention (one thread per pixel) --------
__global__ __launch_bounds__(256) void attn_k(const float* __restrict__ qkv,
                                              float* __restrict__ stacked)
{
    const int i = blockIdx.y;           // dilation index 0..3
    const int b = blockIdx.z;
    const int n = blockIdx.x * 256 + threadIdx.x;
    const int h = n / Ww, w = n % Ww;
    const int r = 1 << i;               // DIL = 1,2,4,8

    const float* qb = qkv + ((size_t)b * 768 + i * 64) * HW;
    const float* kb = qb + (size_t)256 * HW;
    const float* vb = qb + (size_t)512 * HW;

    int noff[9];
#pragma unroll
    for (int dy = 0; dy < 3; dy++)
#pragma unroll
        for (int dx = 0; dx < 3; dx++) {
            int hh = h + (dy - 1) * r, ww = w + (dx - 1) * r;
            noff[dy * 3 + dx] =
                (hh >= 0 && hh < Hh && ww >= 0 && ww < Ww) ? hh * Ww + ww : -1;
        }

    float logit[9];
#pragma unroll
    for (int j = 0; j < 9; j++) logit[j] = 0.f;

    for (int c = 0; c < 64; c++) {
        const float q = qb[(size_t)c * HW + n];
#pragma unroll
        for (int j = 0; j < 9; j++) {
            float kv = (noff[j] >= 0) ? kb[(size_t)c * HW + noff[j]] : 0.f;
            logit[j] += q * kv;
        }
    }

    const float scale = 0.125f;  // hd=64 -> 64^-0.5
    float mx = -1e30f;
#pragma unroll
    for (int j = 0; j < 9; j++) {
        logit[j] *= scale;
        mx = fmaxf(mx, logit[j]);
    }
    float p[9], sum = 0.f;
#pragma unroll
    for (int j = 0; j < 9; j++) { p[j] = __expf(logit[j] - mx); sum += p[j]; }
    const float inv = 1.f / sum;
#pragma unroll
    for (int j = 0; j < 9; j++) p[j] *= inv;

    float* ob = stacked + (((size_t)b * HW + n) * 4 + i) * 64;
    for (int c = 0; c < 64; c++) {
        float o = 0.f;
#pragma unroll
        for (int j = 0; j < 9; j++) {
            float vv = (noff[j] >= 0) ? vb[(size_t)c * HW + noff[j]] : 0.f;
            o += p[j] * vv;
        }
        ob[c] = o;
    }
}

// ---------------- fc scale-fuse + residual + LayerNorm(64) ------------------
__global__ __launch_bounds__(128) void fuse_ln_k(
    const float* __restrict__ stacked, float* __restrict__ y2,
    const float* __restrict__ fc_w, const float* __restrict__ fc_b,
    const float* __restrict__ ln_g, const float* __restrict__ ln_b)
{
    const int p = blockIdx.x;
    const float* sp = stacked + (size_t)p * 256;
    const int t = threadIdx.x >> 5, lane = threadIdx.x & 31;

    float f0 = fc_b[t], f1 = f0;
    float r0 = 0.f, r1 = 0.f;
#pragma unroll
    for (int s = 0; s < 4; s++) {
        float w = fc_w[t * 4 + s];
        float x0 = sp[s * 64 + lane];
        float x1 = sp[s * 64 + lane + 32];
        f0 += w * x0;
        f1 += w * x1;
        if (s == t) { r0 = x0; r1 = x1; }
    }
    f0 += r0;
    f1 += r1;

    float sum = f0 + f1, sq = f0 * f0 + f1 * f1;
#pragma unroll
    for (int o = 16; o; o >>= 1) {
        sum += __shfl_xor_sync(0xffffffffu, sum, o);
        sq  += __shfl_xor_sync(0xffffffffu, sq, o);
    }
    const float mu = sum * (1.f / 64.f);
    const float var = sq * (1.f / 64.f) - mu * mu;
    const float rinv = rsqrtf(var + EPS);

    y2[(size_t)p * 256 + t * 64 + lane] =
        (f0 - mu) * rinv * ln_g[lane] + ln_b[lane];
    y2[(size_t)p * 256 + t * 64 + lane + 32] =
        (f1 - mu) * rinv * ln_g[lane + 32] + ln_b[lane + 32];
}

// ---------------- launch ----------------------------------------------------
extern "C" void kernel_launch(void* const* d_in, const int* in_sizes, int n_in,
                              void* d_out, int out_size)
{
    const float* x      = (const float*)d_in[0];
    const float* qkv_w  = (const float*)d_in[1];
    const float* qkv_b  = (const float*)d_in[2];
    const float* fc_w   = (const float*)d_in[3];
    const float* fc_b   = (const float*)d_in[4];
    const float* ln_g   = (const float*)d_in[5];
    const float* ln_b   = (const float*)d_in[6];
    const float* proj_w = (const float*)d_in[7];
    const float* proj_b = (const float*)d_in[8];
    const float* w1     = (const float*)d_in[9];
    const float* bn1_g  = (const float*)d_in[10];
    const float* bn1_b  = (const float*)d_in[11];
    const float* bn1_m  = (const float*)d_in[12];
    const float* bn1_v  = (const float*)d_in[13];
    const float* w2     = (const float*)d_in[14];
    const float* bn2_g  = (const float*)d_in[15];
    const float* bn2_b  = (const float*)d_in[16];
    const float* bn2_m  = (const float*)d_in[17];
    const float* bn2_v  = (const float*)d_in[18];
    float* out = (float*)d_out;

    void *p_qkv, *p_st, *p_y2, *p_y2t, *p_x1, *p_h, *p_wt;
    cudaGetSymbolAddress(&p_qkv, g_qkv);
    cudaGetSymbolAddress(&p_st, g_stacked);
    cudaGetSymbolAddress(&p_y2, g_y2);
    cudaGetSymbolAddress(&p_y2t, g_y2t);
    cudaGetSymbolAddress(&p_x1, g_x1);
    cudaGetSymbolAddress(&p_h, g_h);
    cudaGetSymbolAddress(&p_wt, g_wt);
    float* qkv = (float*)p_qkv;
    float* stk = (float*)p_st;
    float* y2  = (float*)p_y2;
    float* y2t = (float*)p_y2t;
    float* x1  = (float*)p_x1;
    float* hb  = (float*)p_h;
    float* qkvT = (float*)p_wt;
    float* projT = qkvT + 256 * 768;
    float* w1T   = projT + 256 * 256;
    float* w2T   = w1T + 256 * 512;

    dim3 tb(32, 8);
    // 0) transpose weights: W[M,K] -> Wt[K,M]
    transpose_k<<<dim3(256 / 32, 768 / 32, 1), tb>>>(qkv_w, qkvT, 768, 256);
    transpose_k<<<dim3(256 / 32, 256 / 32, 1), tb>>>(proj_w, projT, 256, 256);
    transpose_k<<<dim3(256 / 32, 512 / 32, 1), tb>>>(w1, w1T, 512, 256);
    transpose_k<<<dim3(512 / 32, 256 / 32, 1), tb>>>(w2, w2T, 256, 512);

    // 1) qkv = qkv_w @ x + qkv_b           (M=768, N=6400, K=256)
    gemm_k<EPI_BIAS><<<dim3(50, 6, Bsz), 256>>>(
        qkvT, x, qkv, 768, HW, 256, qkv_b, nullptr, nullptr, nullptr, nullptr);

    // 2) dilated local attention -> stacked [b,hw,s,c]
    attn_k<<<dim3(25, 4, Bsz), 256>>>(qkv, stk);

    // 3) fc fuse + residual + LN -> y2 [b,hw,256]
    fuse_ln_k<<<Bsz * HW, 128>>>(stk, y2, fc_w, fc_b, ln_g, ln_b);

    // 3b) transpose y2 -> y2t [b,256,hw]
    transpose_k<<<dim3(256 / 32, HW / 32, Bsz), tb>>>(y2, y2t, HW, 256);

    // 4) x1 = x + proj_w @ y2t + proj_b    (M=256, N=6400, K=256)
    gemm_k<EPI_BIAS_ADD><<<dim3(50, 2, Bsz), 256>>>(
        projT, y2t, x1, 256, HW, 256, proj_b, nullptr, nullptr, nullptr, x);

    // 5) h = silu(bn1(w1 @ x1))            (M=512, K=256)
    gemm_k<EPI_BN_SILU><<<dim3(50, 4, Bsz), 256>>>(
        w1T, x1, hb, 512, HW, 256, bn1_g, bn1_b, bn1_m, bn1_v, nullptr);

    // 6) out = x1 + bn2(w2 @ h)            (M=256, K=512)
    gemm_k<EPI_BN_ADD><<<dim3(50, 2, Bsz), 256>>>(
        w2T, hb, out, 256, HW, 512, bn2_g, bn2_b, bn2_m, bn2_v, x1);
}

// round 5
// speedup vs baseline: 1.7156x; 1.2999x over previous
#include <cuda_runtime.h>
#include <cuda_bf16.h>
#include <math.h>
#include <stdint.h>

#define Bsz 8
#define Hh 80
#define Ww 80
#define HW 6400
#define EPS 1e-5f

// ---------------- scratch (device globals; no allocations allowed) ----------
__device__ float g_qkv[(size_t)Bsz * 768 * HW];       // [b,768,hw] channel-major
__device__ float g_stacked[(size_t)Bsz * HW * 256];   // [b,hw,4,64]
__device__ float g_xT[(size_t)Bsz * HW * 256];        // pixel-major fp32
__device__ float g_x1[(size_t)Bsz * HW * 256];        // pixel-major fp32
__device__ __nv_bfloat16 g_xThi[(size_t)Bsz * HW * 256];
__device__ __nv_bfloat16 g_xTlo[(size_t)Bsz * HW * 256];
__device__ __nv_bfloat16 g_y2hi[(size_t)Bsz * HW * 256];
__device__ __nv_bfloat16 g_y2lo[(size_t)Bsz * HW * 256];
__device__ __nv_bfloat16 g_x1hi[(size_t)Bsz * HW * 256];
__device__ __nv_bfloat16 g_x1lo[(size_t)Bsz * HW * 256];
__device__ __nv_bfloat16 g_hhi[(size_t)Bsz * HW * 512];
__device__ __nv_bfloat16 g_hlo[(size_t)Bsz * HW * 512];
#define WTOT (768 * 256 + 256 * 256 + 512 * 256 + 256 * 512)
__device__ __nv_bfloat16 g_whi[WTOT];
__device__ __nv_bfloat16 g_wlo[WTOT];

// ---------------- PTX helpers ------------------------------------------------
__device__ __forceinline__ uint32_t s2u(const void* p) {
    return (uint32_t)__cvta_generic_to_shared(p);
}
__device__ __forceinline__ void cpa16(uint32_t s, const void* g) {
    asm volatile("cp.async.cg.shared.global [%0], [%1], 16;\n" ::"r"(s), "l"(g));
}
#define CP_COMMIT asm volatile("cp.async.commit_group;\n" ::)
#define CP_WAIT1 asm volatile("cp.async.wait_group 1;\n" ::)
#define CP_WAIT0 asm volatile("cp.async.wait_group 0;\n" ::)

#define LDSM4(r, addr)                                                      \
    asm volatile(                                                           \
        "ldmatrix.sync.aligned.m8n8.x4.shared.b16 {%0,%1,%2,%3}, [%4];"     \
        : "=r"((r)[0]), "=r"((r)[1]), "=r"((r)[2]), "=r"((r)[3])            \
        : "r"(addr))

#define MMA(d, a, b0, b1)                                                   \
    asm volatile(                                                           \
        "mma.sync.aligned.m16n8k16.row.col.f32.bf16.bf16.f32 "              \
        "{%0,%1,%2,%3},{%4,%5,%6,%7},{%8,%9},{%0,%1,%2,%3};"                \
        : "+f"((d)[0]), "+f"((d)[1]), "+f"((d)[2]), "+f"((d)[3])            \
        : "r"((a)[0]), "r"((a)[1]), "r"((a)[2]), "r"((a)[3]),               \
          "r"(b0), "r"(b1))

// SMEM geometry: rows of 32 bf16 data + 8 pad = 80B. Tile = 128 rows = 10240B.
#define ROWB 80
#define TILEB 10240
// [buf(2)][half(2)] for A then B; params after.
#define SB_A 0
#define SB_B 40960
#define SPAR 81920
#define SMEM_DYN (81920 + 1024)

enum { EPI_BIAS = 0, EPI_BIAS_ADD = 1, EPI_BN_SILU = 2, EPI_BN_ADD = 3 };

// ---------------- HMMA GEMM --------------------------------------------------
// D[pix, och] = sum_k A[pix,k]*W[och,k]; A,W bf16 hi/lo pairs; fp32 acc.
// 3-term split: Ah*Bh + Ah*Bl + Al*Bh.
template <int EPI, int KTOT, bool CHM, bool OF32, bool OB16>
__global__ __launch_bounds__(256) void mm_k(
    const __nv_bfloat16* __restrict__ Ahi, const __nv_bfloat16* __restrict__ Alo,
    const __nv_bfloat16* __restrict__ Bhi, const __nv_bfloat16* __restrict__ Blo,
    float* of32, __nv_bfloat16* ohi, __nv_bfloat16* olo,
    const float* __restrict__ add,
    const float* __restrict__ q0, const float* __restrict__ q1,
    const float* __restrict__ q2, const float* __restrict__ q3, int OutC)
{
    extern __shared__ char smem[];
    const uint32_t sb = s2u(smem);
    const int tid = threadIdx.x;
    const int wid = tid >> 5, lane = tid & 31;
    const int b = blockIdx.z;
    const int p0 = blockIdx.x * 128;    // pixel tile base
    const int n0g = blockIdx.y * 128;   // out-channel tile base
    constexpr int NC = KTOT / 32;

    const __nv_bfloat16* Abh = Ahi + (size_t)b * HW * KTOT;
    const __nv_bfloat16* Abl = Alo + (size_t)b * HW * KTOT;

    // per-channel epilogue params (128 ch)
    float* sc = (float*)(smem + SPAR);
    float* shf = sc + 128;
    if (tid < 128) {
        const int o = n0g + tid;
        if (EPI == EPI_BIAS || EPI == EPI_BIAS_ADD) {
            sc[tid] = 1.f; shf[tid] = q0[o];
        } else {
            float inv = q0[o] * rsqrtf(q3[o] + EPS);
            sc[tid] = inv; shf[tid] = q1[o] - q2[o] * inv;
        }
    }

    // loader indices: pos = row*4 + c16
    const int lrow = tid >> 2, lc16 = tid & 3;

    auto issue = [&](int c) {
        const int koff = c * 32;
        const uint32_t bs = (c & 1) ? TILEB * 2 : 0;
#pragma unroll
        for (int rep = 0; rep < 2; rep++) {
            const int row = lrow + rep * 64;
            const uint32_t so = bs + row * ROWB + lc16 * 16;
            const size_t ga = (size_t)(p0 + row) * KTOT + koff + lc16 * 8;
            cpa16(sb + SB_A + so, Abh + ga);
            cpa16(sb + SB_A + TILEB + so, Abl + ga);
            const size_t gb = (size_t)(n0g + row) * KTOT + koff + lc16 * 8;
            cpa16(sb + SB_B + so, Bhi + gb);
            cpa16(sb + SB_B + TILEB + so, Blo + gb);
        }
        CP_COMMIT;
    };

    const int warp_m = wid >> 2, warp_n = wid & 3;
    const uint32_t rowA = (warp_m * 64 + (lane & 15)) * ROWB + (lane >> 4) * 16;
    const uint32_t rowB = (warp_n * 32 + (lane & 15)) * ROWB + (lane >> 4) * 16;

    float acc[4][4][4];
#pragma unroll
    for (int f = 0; f < 4; f++)
#pragma unroll
        for (int g = 0; g < 4; g++)
#pragma unroll
            for (int j = 0; j < 4; j++) acc[f][g][j] = 0.f;

    issue(0);
    for (int c = 0; c < NC; c++) {
        if (c + 1 < NC) { issue(c + 1); CP_WAIT1; }
        else { CP_WAIT0; }
        __syncthreads();
        const uint32_t bs = (c & 1) ? TILEB * 2 : 0;
        const uint32_t ah = sb + SB_A + bs, al = ah + TILEB;
        const uint32_t bh = sb + SB_B + bs, bl = bh + TILEB;
#pragma unroll
        for (int s = 0; s < 2; s++) {
            uint32_t Ah[4][4], Al[4][4], Bh[2][4], Bl[2][4];
#pragma unroll
            for (int f = 0; f < 4; f++) {
                LDSM4(Ah[f], ah + rowA + f * (16 * ROWB) + s * 32);
                LDSM4(Al[f], al + rowA + f * (16 * ROWB) + s * 32);
            }
#pragma unroll
            for (int g = 0; g < 2; g++) {
                LDSM4(Bh[g], bh + rowB + g * (16 * ROWB) + s * 32);
                LDSM4(Bl[g], bl + rowB + g * (16 * ROWB) + s * 32);
            }
#pragma unroll
            for (int f = 0; f < 4; f++)
#pragma unroll
                for (int g = 0; g < 2; g++) {
                    MMA(acc[f][2 * g + 0], Ah[f], Bh[g][0], Bh[g][2]);
                    MMA(acc[f][2 * g + 1], Ah[f], Bh[g][1], Bh[g][3]);
                    MMA(acc[f][2 * g + 0], Ah[f], Bl[g][0], Bl[g][2]);
                    MMA(acc[f][2 * g + 1], Ah[f], Bl[g][1], Bl[g][3]);
                    MMA(acc[f][2 * g + 0], Al[f], Bh[g][0], Bh[g][2]);
                    MMA(acc[f][2 * g + 1], Al[f], Bh[g][1], Bh[g][3]);
                }
        }
        __syncthreads();
    }

    // ---- epilogue ----
    float* of32b = OF32 ? (CHM ? of32 + (size_t)b * OutC * HW
                               : of32 + (size_t)b * HW * OutC) : nullptr;
    __nv_bfloat16* ohb = OB16 ? ohi + (size_t)b * HW * OutC : nullptr;
    __nv_bfloat16* olb = OB16 ? olo + (size_t)b * HW * OutC : nullptr;
    const float* addb = (EPI == EPI_BIAS_ADD || EPI == EPI_BN_ADD)
                            ? add + (size_t)b * HW * 256 : nullptr;
    float(*st)[132] = (float(*)[132])smem;  // CHM staging (67.6KB < 80KB tiles)

#pragma unroll
    for (int f = 0; f < 4; f++)
#pragma unroll
        for (int g = 0; g < 4; g++)
#pragma unroll
            for (int hp = 0; hp < 2; hp++) {
                const int m = warp_m * 64 + f * 16 + (lane >> 2) + hp * 8;
                const int n = warp_n * 32 + g * 8 + (lane & 3) * 2;
                float v0 = acc[f][g][hp * 2 + 0];
                float v1 = acc[f][g][hp * 2 + 1];
                v0 = v0 * sc[n] + shf[n];
                v1 = v1 * sc[n + 1] + shf[n + 1];
                if (EPI == EPI_BN_SILU) {
                    v0 = v0 / (1.f + __expf(-v0));
                    v1 = v1 / (1.f + __expf(-v1));
                }
                if (EPI == EPI_BIAS_ADD || EPI == EPI_BN_ADD) {
                    float2 a2 = *(const float2*)(addb + (size_t)(p0 + m) * 256 + n0g + n);
                    v0 += a2.x; v1 += a2.y;
                }
                if (CHM) {
                    st[m][n] = v0; st[m][n + 1] = v1;
                } else {
                    const size_t base = (size_t)(p0 + m) * OutC + n0g + n;
                    if (OF32) *(float2*)(of32b + base) = make_float2(v0, v1);
                    if (OB16) {
                        __nv_bfloat16 h0 = __float2bfloat16(v0);
                        __nv_bfloat16 h1 = __float2bfloat16(v1);
                        __nv_bfloat162 hp2; hp2.x = h0; hp2.y = h1;
                        __nv_bfloat162 lp2;
                        lp2.x = __float2bfloat16(v0 - __bfloat162float(h0));
                        lp2.y = __float2bfloat16(v1 - __bfloat162float(h1));
                        *(__nv_bfloat162*)(ohb + base) = hp2;
                        *(__nv_bfloat162*)(olb + base) = lp2;
                    }
                }
            }

    if (CHM) {
        __syncthreads();
        for (int i = tid; i < 128 * 32; i += 256) {
            const int ch = i >> 5;
            const int px = (i & 31) * 4;
            float4 o4 = make_float4(st[px][ch], st[px + 1][ch],
                                    st[px + 2][ch], st[px + 3][ch]);
            *(float4*)(of32b + (size_t)(n0g + ch) * HW + p0 + px) = o4;
        }
    }
}

// ---------------- x transpose + bf16 split ----------------------------------
__global__ void xconv_k(const float* __restrict__ x, float* __restrict__ xT,
                        __nv_bfloat16* __restrict__ xhi, __nv_bfloat16* __restrict__ xlo)
{
    __shared__ float t[32][33];
    const int b = blockIdx.z;
    const int nb = blockIdx.x * 32, cb = blockIdx.y * 32;
    const int tx = threadIdx.x, ty = threadIdx.y;
#pragma unroll
    for (int i = ty; i < 32; i += 8)
        t[i][tx] = x[(size_t)b * 256 * HW + (size_t)(cb + i) * HW + nb + tx];
    __syncthreads();
#pragma unroll
    for (int i = ty; i < 32; i += 8) {
        float v = t[tx][i];
        size_t idx = (size_t)b * HW * 256 + (size_t)(nb + i) * 256 + cb + tx;
        xT[idx] = v;
        __nv_bfloat16 h = __float2bfloat16(v);
        xhi[idx] = h;
        xlo[idx] = __float2bfloat16(v - __bfloat162float(h));
    }
}

// ---------------- weight bf16 split -----------------------------------------
__global__ void wconv_k(const float* __restrict__ w, __nv_bfloat16* __restrict__ hi,
                        __nv_bfloat16* __restrict__ lo, int n)
{
    int i = blockIdx.x * 256 + threadIdx.x;
    if (i < n) {
        float v = w[i];
        __nv_bfloat16 h = __float2bfloat16(v);
        hi[i] = h;
        lo[i] = __float2bfloat16(v - __bfloat162float(h));
    }
}

// ---------------- dilated 3x3 local attention --------------------------------
__global__ __launch_bounds__(256) void attn_k(const float* __restrict__ qkv,
                                              float* __restrict__ stacked)
{
    const int i = blockIdx.y;
    const int b = blockIdx.z;
    const int n = blockIdx.x * 256 + threadIdx.x;
    const int h = n / Ww, w = n % Ww;
    const int r = 1 << i;

    const float* qb = qkv + ((size_t)b * 768 + i * 64) * HW;
    const float* kb = qb + (size_t)256 * HW;
    const float* vb = qb + (size_t)512 * HW;

    int noff[9];
#pragma unroll
    for (int dy = 0; dy < 3; dy++)
#pragma unroll
        for (int dx = 0; dx < 3; dx++) {
            int hh = h + (dy - 1) * r, ww = w + (dx - 1) * r;
            noff[dy * 3 + dx] =
                (hh >= 0 && hh < Hh && ww >= 0 && ww < Ww) ? hh * Ww + ww : -1;
        }

    float logit[9];
#pragma unroll
    for (int j = 0; j < 9; j++) logit[j] = 0.f;

    for (int c = 0; c < 64; c++) {
        const float q = qb[(size_t)c * HW + n];
#pragma unroll
        for (int j = 0; j < 9; j++) {
            float kv = (noff[j] >= 0) ? kb[(size_t)c * HW + noff[j]] : 0.f;
            logit[j] += q * kv;
        }
    }

    const float scale = 0.125f;
    float mx = -1e30f;
#pragma unroll
    for (int j = 0; j < 9; j++) { logit[j] *= scale; mx = fmaxf(mx, logit[j]); }
    float p[9], sum = 0.f;
#pragma unroll
    for (int j = 0; j < 9; j++) { p[j] = __expf(logit[j] - mx); sum += p[j]; }
    const float inv = 1.f / sum;
#pragma unroll
    for (int j = 0; j < 9; j++) p[j] *= inv;

    float* ob = stacked + (((size_t)b * HW + n) * 4 + i) * 64;
    for (int c = 0; c < 64; c++) {
        float o = 0.f;
#pragma unroll
        for (int j = 0; j < 9; j++) {
            float vv = (noff[j] >= 0) ? vb[(size_t)c * HW + noff[j]] : 0.f;
            o += p[j] * vv;
        }
        ob[c] = o;
    }
}

// ---------------- fc scale-fuse + residual + LayerNorm(64) → bf16 hi/lo -----
__global__ __launch_bounds__(128) void fuse_ln_k(
    const float* __restrict__ stacked,
    __nv_bfloat16* __restrict__ y2hi, __nv_bfloat16* __restrict__ y2lo,
    const float* __restrict__ fc_w, const float* __restrict__ fc_b,
    const float* __restrict__ ln_g, const float* __restrict__ ln_b)
{
    const int p = blockIdx.x;
    const float* sp = stacked + (size_t)p * 256;
    const int t = threadIdx.x >> 5, lane = threadIdx.x & 31;

    float f0 = fc_b[t], f1 = f0;
    float r0 = 0.f, r1 = 0.f;
#pragma unroll
    for (int s = 0; s < 4; s++) {
        float w = fc_w[t * 4 + s];
        float x0 = sp[s * 64 + lane];
        float x1 = sp[s * 64 + lane + 32];
        f0 += w * x0;
        f1 += w * x1;
        if (s == t) { r0 = x0; r1 = x1; }
    }
    f0 += r0;
    f1 += r1;

    float sum = f0 + f1, sq = f0 * f0 + f1 * f1;
#pragma unroll
    for (int o = 16; o; o >>= 1) {
        sum += __shfl_xor_sync(0xffffffffu, sum, o);
        sq  += __shfl_xor_sync(0xffffffffu, sq, o);
    }
    const float mu = sum * (1.f / 64.f);
    const float var = sq * (1.f / 64.f) - mu * mu;
    const float rinv = rsqrtf(var + EPS);

    float o0 = (f0 - mu) * rinv * ln_g[lane] + ln_b[lane];
    float o1 = (f1 - mu) * rinv * ln_g[lane + 32] + ln_b[lane + 32];
    size_t i0 = (size_t)p * 256 + t * 64 + lane;
    __nv_bfloat16 h0 = __float2bfloat16(o0);
    __nv_bfloat16 h1 = __float2bfloat16(o1);
    y2hi[i0] = h0;
    y2hi[i0 + 32] = h1;
    y2lo[i0] = __float2bfloat16(o0 - __bfloat162float(h0));
    y2lo[i0 + 32] = __float2bfloat16(o1 - __bfloat162float(h1));
}

// ---------------- launch ----------------------------------------------------
extern "C" void kernel_launch(void* const* d_in, const int* in_sizes, int n_in,
                              void* d_out, int out_size)
{
    const float* x      = (const float*)d_in[0];
    const float* qkv_w  = (const float*)d_in[1];
    const float* qkv_b  = (const float*)d_in[2];
    const float* fc_w   = (const float*)d_in[3];
    const float* fc_b   = (const float*)d_in[4];
    const float* ln_g   = (const float*)d_in[5];
    const float* ln_b   = (const float*)d_in[6];
    const float* proj_w = (const float*)d_in[7];
    const float* proj_b = (const float*)d_in[8];
    const float* w1     = (const float*)d_in[9];
    const float* bn1_g  = (const float*)d_in[10];
    const float* bn1_b  = (const float*)d_in[11];
    const float* bn1_m  = (const float*)d_in[12];
    const float* bn1_v  = (const float*)d_in[13];
    const float* w2     = (const float*)d_in[14];
    const float* bn2_g  = (const float*)d_in[15];
    const float* bn2_b  = (const float*)d_in[16];
    const float* bn2_m  = (const float*)d_in[17];
    const float* bn2_v  = (const float*)d_in[18];
    float* out = (float*)d_out;

    void *p_qkv, *p_st, *p_xT, *p_x1, *p_xThi, *p_xTlo, *p_y2hi, *p_y2lo,
        *p_x1hi, *p_x1lo, *p_hhi, *p_hlo, *p_whi, *p_wlo;
    cudaGetSymbolAddress(&p_qkv, g_qkv);
    cudaGetSymbolAddress(&p_st, g_stacked);
    cudaGetSymbolAddress(&p_xT, g_xT);
    cudaGetSymbolAddress(&p_x1, g_x1);
    cudaGetSymbolAddress(&p_xThi, g_xThi);
    cudaGetSymbolAddress(&p_xTlo, g_xTlo);
    cudaGetSymbolAddress(&p_y2hi, g_y2hi);
    cudaGetSymbolAddress(&p_y2lo, g_y2lo);
    cudaGetSymbolAddress(&p_x1hi, g_x1hi);
    cudaGetSymbolAddress(&p_x1lo, g_x1lo);
    cudaGetSymbolAddress(&p_hhi, g_hhi);
    cudaGetSymbolAddress(&p_hlo, g_hlo);
    cudaGetSymbolAddress(&p_whi, g_whi);
    cudaGetSymbolAddress(&p_wlo, g_wlo);

    float* qkv = (float*)p_qkv;
    float* stk = (float*)p_st;
    float* xT  = (float*)p_xT;
    float* x1  = (float*)p_x1;
    __nv_bfloat16* xThi = (__nv_bfloat16*)p_xThi;
    __nv_bfloat16* xTlo = (__nv_bfloat16*)p_xTlo;
    __nv_bfloat16* y2hi = (__nv_bfloat16*)p_y2hi;
    __nv_bfloat16* y2lo = (__nv_bfloat16*)p_y2lo;
    __nv_bfloat16* x1hi = (__nv_bfloat16*)p_x1hi;
    __nv_bfloat16* x1lo = (__nv_bfloat16*)p_x1lo;
    __nv_bfloat16* hhi = (__nv_bfloat16*)p_hhi;
    __nv_bfloat16* hlo = (__nv_bfloat16*)p_hlo;
    __nv_bfloat16* whi = (__nv_bfloat16*)p_whi;
    __nv_bfloat16* wlo = (__nv_bfloat16*)p_wlo;

    __nv_bfloat16* qkvWhi = whi;
    __nv_bfloat16* projWhi = qkvWhi + 768 * 256;
    __nv_bfloat16* w1hi = projWhi + 256 * 256;
    __nv_bfloat16* w2hi = w1hi + 512 * 256;
    __nv_bfloat16* qkvWlo = wlo;
    __nv_bfloat16* projWlo = qkvWlo + 768 * 256;
    __nv_bfloat16* w1lo = projWlo + 256 * 256;
    __nv_bfloat16* w2lo = w1lo + 512 * 256;

    auto kqkv = mm_k<EPI_BIAS, 256, true, true, false>;
    auto kproj = mm_k<EPI_BIAS_ADD, 256, false, true, true>;
    auto kw1 = mm_k<EPI_BN_SILU, 256, false, false, true>;
    auto kw2 = mm_k<EPI_BN_ADD, 512, true, true, false>;
    cudaFuncSetAttribute(kqkv, cudaFuncAttributeMaxDynamicSharedMemorySize, SMEM_DYN);
    cudaFuncSetAttribute(kproj, cudaFuncAttributeMaxDynamicSharedMemorySize, SMEM_DYN);
    cudaFuncSetAttribute(kw1, cudaFuncAttributeMaxDynamicSharedMemorySize, SMEM_DYN);
    cudaFuncSetAttribute(kw2, cudaFuncAttributeMaxDynamicSharedMemorySize, SMEM_DYN);

    // 0) weight + input conversions
    wconv_k<<<(768 * 256 + 255) / 256, 256>>>(qkv_w, qkvWhi, qkvWlo, 768 * 256);
    wconv_k<<<(256 * 256 + 255) / 256, 256>>>(proj_w, projWhi, projWlo, 256 * 256);
    wconv_k<<<(512 * 256 + 255) / 256, 256>>>(w1, w1hi, w1lo, 512 * 256);
    wconv_k<<<(256 * 512 + 255) / 256, 256>>>(w2, w2hi, w2lo, 256 * 512);
    xconv_k<<<dim3(HW / 32, 256 / 32, Bsz), dim3(32, 8)>>>(x, xT, xThi, xTlo);

    // 1) qkv = qkv_w @ x + b  -> channel-major fp32 [b,768,hw]
    kqkv<<<dim3(50, 6, Bsz), 256, SMEM_DYN>>>(
        xThi, xTlo, qkvWhi, qkvWlo, qkv, nullptr, nullptr, nullptr,
        qkv_b, nullptr, nullptr, nullptr, 768);

    // 2) dilated local attention
    attn_k<<<dim3(25, 4, Bsz), 256>>>(qkv, stk);

    // 3) fc fuse + residual + LN -> y2 bf16 hi/lo (pixel-major)
    fuse_ln_k<<<Bsz * HW, 128>>>(stk, y2hi, y2lo, fc_w, fc_b, ln_g, ln_b);

    // 4) x1 = xT + proj(y2)  -> fp32 + bf16 hi/lo, pixel-major
    kproj<<<dim3(50, 2, Bsz), 256, SMEM_DYN>>>(
        y2hi, y2lo, projWhi, projWlo, x1, x1hi, x1lo, xT,
        proj_b, nullptr, nullptr, nullptr, 256);

    // 5) h = silu(bn1(w1 @ x1)) -> bf16 hi/lo, pixel-major
    kw1<<<dim3(50, 4, Bsz), 256, SMEM_DYN>>>(
        x1hi, x1lo, w1hi, w1lo, nullptr, hhi, hlo, nullptr,
        bn1_g, bn1_b, bn1_m, bn1_v, 512);

    // 6) out = x1 + bn2(w2 @ h) -> channel-major fp32 (d_out)
    kw2<<<dim3(50, 2, Bsz), 256, SMEM_DYN>>>(
        hhi, hlo, w2hi, w2lo, out, nullptr, nullptr, x1,
        bn2_g, bn2_b, bn2_m, bn2_v, 256);
}